// round 9
// baseline (speedup 1.0000x reference)
#include <cuda_runtime.h>
#include <cuda_fp16.h>
#include <cstdint>

// ---------------------------------------------------------------------------
// PositionAttentionModule: B=4, HW=4096, C=512, Cr=64
//   q|k = x@[W1|W2]      fp32 SGEMM (proven)
//   split q,k            fp32 -> (hi,lo) fp16 pairs
//   v   = x@W3           f16 HMMA NT (proven) -> vT fp16
//   attn_probs           FUSED: 3-term split QK^T + online softmax (2-pass,
//                        FMA-pipe exp2 poly) -> fp16 probs. No fp32 logits.
//   E = s @ v            f16 HMMA NT (proven), fused gamma*E + x
// Rule R7: device globals referenced ONLY inside kernel bodies.
// ---------------------------------------------------------------------------

constexpr int kHW  = 4096;
constexpr int kC   = 512;
constexpr int kTok = 4 * kHW;   // 16384

__device__ float  g_qk  [kTok * 128];                   // 8 MB (q | k) fp32
__device__ __half g_qs  [kTok * 128];                   // 4 MB q split [hi|lo]
__device__ __half g_ks  [kTok * 128];                   // 4 MB k split [hi|lo]
__device__ float  g_w12 [kC * 128];                     // 256 KB
__device__ __half g_sh  [(size_t)4 * kHW * kHW];        // 128 MB fp16 probs
__device__ __half g_vT  [(size_t)4 * kC * kHW];         // 16 MB vT[b][n][i]
__device__ __half g_xh  [(size_t)kTok * kC];            // 16 MB x fp16 [m][k]
__device__ __half g_w3T [kC * kC];                      // 512 KB W3^T fp16 [n][k]

// ============================ PTX helpers ==================================
__device__ __forceinline__ uint32_t smem_u32(const void* p) {
    uint32_t a;
    asm("{ .reg .u64 t; cvta.to.shared.u64 t, %1; cvt.u32.u64 %0, t; }"
        : "=r"(a) : "l"(p));
    return a;
}
__device__ __forceinline__ void ldmx4(uint32_t& r0, uint32_t& r1, uint32_t& r2,
                                      uint32_t& r3, uint32_t a) {
    asm volatile("ldmatrix.sync.aligned.m8n8.x4.shared.b16 {%0,%1,%2,%3}, [%4];"
                 : "=r"(r0), "=r"(r1), "=r"(r2), "=r"(r3) : "r"(a));
}
__device__ __forceinline__ void mma16816(float* c, const uint32_t* a,
                                         const uint32_t* b) {
    asm volatile(
        "mma.sync.aligned.m16n8k16.row.col.f32.f16.f16.f32 "
        "{%0,%1,%2,%3}, {%4,%5,%6,%7}, {%8,%9}, {%0,%1,%2,%3};"
        : "+f"(c[0]), "+f"(c[1]), "+f"(c[2]), "+f"(c[3])
        : "r"(a[0]), "r"(a[1]), "r"(a[2]), "r"(a[3]), "r"(b[0]), "r"(b[1]));
}
#define CP16(sm, gp) \
    asm volatile("cp.async.cg.shared.global [%0], [%1], 16;" :: "r"(sm), "l"(gp))
#define CP_COMMIT() asm volatile("cp.async.commit_group;" ::: "memory")
#define CP_WAIT(n)  asm volatile("cp.async.wait_group %0;" :: "n"(n) : "memory")

// exp2 on the FMA pipe (degree-7 Taylor, rel err ~2e-7), f <= ~0 expected
__device__ __forceinline__ float exp2f_fast(float f) {
    f = fmaxf(f, -126.f);
    float n = floorf(f);
    float r = f - n;
    float p = 1.5252734e-5f;
    p = fmaf(p, r, 1.5403530e-4f);
    p = fmaf(p, r, 1.3333558e-3f);
    p = fmaf(p, r, 9.6181291e-3f);
    p = fmaf(p, r, 5.5504109e-2f);
    p = fmaf(p, r, 2.4022651e-1f);
    p = fmaf(p, r, 6.9314718e-1f);
    p = fmaf(p, r, 1.0f);
    return p * __int_as_float((((int)n) + 127) << 23);
}
constexpr float LOG2E = 1.4426950408889634f;

// ---------------------------------------------------------------------------
__global__ __launch_bounds__(256) void concat_w(const float* __restrict__ W1,
                                                const float* __restrict__ W2) {
    int idx = blockIdx.x * 256 + threadIdx.x;
    int n = idx & 127;
    int k = idx >> 7;
    g_w12[idx] = (n < 64) ? W1[(k << 6) + n] : W2[(k << 6) + (n - 64)];
}

__global__ __launch_bounds__(256) void to_half_x(const float* __restrict__ x) {
    int idx = blockIdx.x * 256 + threadIdx.x;
    float4 v = *(const float4*)(x + (size_t)idx * 4);
    __half2* d = (__half2*)(g_xh + (size_t)idx * 4);
    d[0] = __floats2half2_rn(v.x, v.y);
    d[1] = __floats2half2_rn(v.z, v.w);
}

__global__ __launch_bounds__(256) void transpose_w3(const float* __restrict__ W3) {
    __shared__ float t[32][33];
    const int tx = threadIdx.x & 31, ty = threadIdx.x >> 5;
    const int n0 = blockIdx.x * 32;
    const int k0 = blockIdx.y * 32;
    #pragma unroll
    for (int j = 0; j < 4; j++) {
        int kk = ty + j * 8;
        t[kk][tx] = W3[(size_t)(k0 + kk) * kC + n0 + tx];
    }
    __syncthreads();
    #pragma unroll
    for (int j = 0; j < 4; j++) {
        int nn = ty + j * 8;
        g_w3T[(size_t)(n0 + nn) * kC + k0 + tx] = __float2half_rn(t[tx][nn]);
    }
}

__global__ __launch_bounds__(256) void split_qk() {
    int idx = blockIdx.x * 256 + threadIdx.x;
    int t = idx >> 7, c = idx & 127;
    float v = g_qk[idx];
    __half hi = __float2half_rn(v);
    __half lo = __float2half_rn(v - __half2float(hi));
    if (c < 64) {
        g_qs[t * 128 + c]      = hi;
        g_qs[t * 128 + 64 + c] = lo;
    } else {
        g_ks[t * 128 + c - 64] = hi;
        g_ks[t * 128 + c]      = lo;
    }
}

// ======================= fp32 SGEMM scaffolding (proven) ===================
#define GEMM_DECL()                                                            \
    __shared__ float As[2][8][132];                                            \
    __shared__ float Bs[2][8][132];                                            \
    const int tid = threadIdx.x;                                               \
    const int a_r = tid >> 1, a_c = (tid & 1) << 2;                            \
    const int ty  = tid >> 4, tx  = tid & 15;                                  \
    float acc[8][8];                                                           \
    _Pragma("unroll") for (int i = 0; i < 8; i++)                              \
        _Pragma("unroll") for (int j = 0; j < 8; j++) acc[i][j] = 0.f;

#define STORE_A_TILE(buf, v)                                                   \
    As[buf][a_c + 0][a_r] = (v).x; As[buf][a_c + 1][a_r] = (v).y;              \
    As[buf][a_c + 2][a_r] = (v).z; As[buf][a_c + 3][a_r] = (v).w;

#define COMPUTE_KSTEPS(buf)                                                    \
    _Pragma("unroll") for (int kk = 0; kk < 8; kk++) {                         \
        float4 a0 = *(const float4*)&As[buf][kk][(ty << 2)];                   \
        float4 a1 = *(const float4*)&As[buf][kk][64 + (ty << 2)];              \
        float4 b0 = *(const float4*)&Bs[buf][kk][(tx << 2)];                   \
        float4 b1 = *(const float4*)&Bs[buf][kk][64 + (tx << 2)];              \
        float af[8]  = {a0.x, a0.y, a0.z, a0.w, a1.x, a1.y, a1.z, a1.w};       \
        float bfr[8] = {b0.x, b0.y, b0.z, b0.w, b1.x, b1.y, b1.z, b1.w};       \
        _Pragma("unroll") for (int i = 0; i < 8; i++)                          \
            _Pragma("unroll") for (int j = 0; j < 8; j++)                      \
                acc[i][j] = fmaf(af[i], bfr[j], acc[i][j]);                    \
    }

// q|k projection (proven): g_qk = x @ g_w12, fp32
__global__ __launch_bounds__(256, 2) void proj_gemm(const float* __restrict__ x) {
    GEMM_DECL();
    const int b_r = tid >> 5, b_c = (tid & 31) << 2;
    const float* Ab = x + (size_t)(blockIdx.y * 128 + a_r) * 512 + a_c;
    const float* Bb = (const float*)g_w12 + (size_t)b_r * 128 + b_c;

    float4 av = *(const float4*)Ab;
    float4 bv = *(const float4*)Bb;
    STORE_A_TILE(0, av);
    *(float4*)&Bs[0][b_r][b_c] = bv;
    __syncthreads();

    int buf = 0;
    for (int k0 = 8; k0 <= 512; k0 += 8) {
        if (k0 < 512) {
            av = *(const float4*)(Ab + k0);
            bv = *(const float4*)(Bb + (size_t)k0 * 128);
        }
        COMPUTE_KSTEPS(buf);
        if (k0 < 512) {
            buf ^= 1;
            STORE_A_TILE(buf, av);
            *(float4*)&Bs[buf][b_r][b_c] = bv;
            __syncthreads();
        }
    }

    const int row0 = blockIdx.y * 128;
    const int c0 = (tx << 2);
    #pragma unroll
    for (int i = 0; i < 8; i++) {
        int r = row0 + ((i < 4) ? (ty << 2) + i : 64 + (ty << 2) + (i - 4));
        *(float4*)(g_qk + (size_t)r * 128 + c0)      = make_float4(acc[i][0], acc[i][1], acc[i][2], acc[i][3]);
        *(float4*)(g_qk + (size_t)r * 128 + c0 + 64) = make_float4(acc[i][4], acc[i][5], acc[i][6], acc[i][7]);
    }
}

// ============ HMMA NT skeleton constants (pv & vproj) ======================
constexpr int PV_LDA  = 72;                         // halves, padded
constexpr int PV_ABUF = 128 * PV_LDA * 2;           // 18432 B
constexpr int PV_SMEM = 4 * PV_ABUF;                // 73728 B

// ====================== HMMA: PV (E = s @ v), fused epilogue (proven) ======
__global__ void __launch_bounds__(256, 2)
pv_mma(const float* __restrict__ x, const float* __restrict__ gamma,
       float* __restrict__ out) {
    extern __shared__ char smem[];
    const uint32_t sb  = smem_u32(smem);
    const int tid  = threadIdx.x;
    const int lane = tid & 31, wid = tid >> 5;
    const int wm = (wid & 1) * 64, wn = (wid >> 1) * 32;
    const int n0 = blockIdx.x * 128, m0 = blockIdx.y * 128, bz = blockIdx.z;

    const __half* Asrc = g_sh + (size_t)bz * kHW * kHW + (size_t)m0 * kHW;
    const __half* Bsrc = g_vT + (size_t)bz * kC * kHW + (size_t)n0 * kHW;

    const uint32_t sA[2] = {sb, sb + PV_ABUF};
    const uint32_t sB[2] = {sb + 2 * PV_ABUF, sb + 3 * PV_ABUF};

    const int ldrow  = tid >> 3;
    const int ldslot = (tid & 7) * 8;

    float acc[4][4][4];
    #pragma unroll
    for (int i = 0; i < 4; i++)
        #pragma unroll
        for (int j = 0; j < 4; j++)
            #pragma unroll
            for (int r = 0; r < 4; r++) acc[i][j][r] = 0.f;

    const int aRow = wm + (lane & 15);
    const int aCol = (lane >> 4) * 8;
    const int bRow = wn + ((lane >> 4) << 3) + (lane & 7);
    const int bCol = ((lane >> 3) & 1) * 8;

    #pragma unroll
    for (int q = 0; q < 4; q++) {
        int r = q * 32 + ldrow;
        CP16(sA[0] + (r * PV_LDA + ldslot) * 2, Asrc + (size_t)r * kHW + ldslot);
        CP16(sB[0] + (r * PV_LDA + ldslot) * 2, Bsrc + (size_t)r * kHW + ldslot);
    }
    CP_COMMIT();

    for (int i = 0; i < 64; i++) {
        const int buf = i & 1;
        if (i < 63) {
            const int k0 = (i + 1) * 64;
            #pragma unroll
            for (int q = 0; q < 4; q++) {
                int r = q * 32 + ldrow;
                CP16(sA[buf ^ 1] + (r * PV_LDA + ldslot) * 2,
                     Asrc + (size_t)r * kHW + k0 + ldslot);
                CP16(sB[buf ^ 1] + (r * PV_LDA + ldslot) * 2,
                     Bsrc + (size_t)r * kHW + k0 + ldslot);
            }
            CP_COMMIT();
            CP_WAIT(1);
        } else {
            CP_WAIT(0);
        }
        __syncthreads();

        #pragma unroll
        for (int ks = 0; ks < 4; ks++) {
            uint32_t af[4][4], bf[4][2];
            #pragma unroll
            for (int mt = 0; mt < 4; mt++)
                ldmx4(af[mt][0], af[mt][1], af[mt][2], af[mt][3],
                      sA[buf] + ((aRow + mt * 16) * PV_LDA + aCol + ks * 16) * 2);
            #pragma unroll
            for (int np = 0; np < 2; np++)
                ldmx4(bf[np * 2][0], bf[np * 2][1], bf[np * 2 + 1][0], bf[np * 2 + 1][1],
                      sB[buf] + ((bRow + np * 16) * PV_LDA + bCol + ks * 16) * 2);
            #pragma unroll
            for (int mt = 0; mt < 4; mt++)
                #pragma unroll
                for (int nt = 0; nt < 4; nt++)
                    mma16816(acc[mt][nt], af[mt], bf[nt]);
        }
        __syncthreads();
    }

    float* stage = (float*)smem;          // [128][132] as [n][m]
    #pragma unroll
    for (int mt = 0; mt < 4; mt++)
        #pragma unroll
        for (int nt = 0; nt < 4; nt++)
            #pragma unroll
            for (int r = 0; r < 4; r++) {
                int m = wm + mt * 16 + (lane >> 2) + ((r >= 2) ? 8 : 0);
                int n = wn + nt * 8 + (lane & 3) * 2 + (r & 1);
                stage[n * 132 + m] = acc[mt][nt][r];
            }
    __syncthreads();

    const float g = __ldg(gamma);
    const size_t obofs = (size_t)bz * kHW * kC;
    #pragma unroll
    for (int q = 0; q < 16; q++) {
        int idx = tid + q * 256;
        int n   = idx >> 5;
        int m4  = (idx & 31) << 2;
        size_t o = obofs + (size_t)(n0 + n) * kHW + m0 + m4;
        float4 xv = *(const float4*)(x + o);
        const float* sp = stage + n * 132 + m4;
        *(float4*)(out + o) = make_float4(fmaf(g, sp[0], xv.x), fmaf(g, sp[1], xv.y),
                                          fmaf(g, sp[2], xv.z), fmaf(g, sp[3], xv.w));
    }
}

// ============ HMMA: V-proj NT (proven): vT = (x @ W3)^T ====================
__global__ void __launch_bounds__(256, 2) void_decl_guard();
__global__ void __launch_bounds__(256, 2) vproj_mma() {
    extern __shared__ char smem[];
    const uint32_t sb  = smem_u32(smem);
    const int tid  = threadIdx.x;
    const int lane = tid & 31, wid = tid >> 5;
    const int wm = (wid & 1) * 64, wn = (wid >> 1) * 32;
    const int n0 = blockIdx.x * 128, m0 = blockIdx.y * 128;

    const __half* Asrc = g_xh + (size_t)m0 * kC;
    const __half* Bsrc = g_w3T + (size_t)n0 * kC;

    const uint32_t sA[2] = {sb, sb + PV_ABUF};
    const uint32_t sB[2] = {sb + 2 * PV_ABUF, sb + 3 * PV_ABUF};

    const int ldrow  = tid >> 3;
    const int ldslot = (tid & 7) * 8;

    float acc[4][4][4];
    #pragma unroll
    for (int i = 0; i < 4; i++)
        #pragma unroll
        for (int j = 0; j < 4; j++)
            #pragma unroll
            for (int r = 0; r < 4; r++) acc[i][j][r] = 0.f;

    const int aRow = wm + (lane & 15);
    const int aCol = (lane >> 4) * 8;
    const int bRow = wn + ((lane >> 4) << 3) + (lane & 7);
    const int bCol = ((lane >> 3) & 1) * 8;

    #pragma unroll
    for (int q = 0; q < 4; q++) {
        int r = q * 32 + ldrow;
        CP16(sA[0] + (r * PV_LDA + ldslot) * 2, Asrc + (size_t)r * kC + ldslot);
        CP16(sB[0] + (r * PV_LDA + ldslot) * 2, Bsrc + (size_t)r * kC + ldslot);
    }
    CP_COMMIT();

    for (int i = 0; i < 8; i++) {
        const int buf = i & 1;
        if (i < 7) {
            const int k0 = (i + 1) * 64;
            #pragma unroll
            for (int q = 0; q < 4; q++) {
                int r = q * 32 + ldrow;
                CP16(sA[buf ^ 1] + (r * PV_LDA + ldslot) * 2,
                     Asrc + (size_t)r * kC + k0 + ldslot);
                CP16(sB[buf ^ 1] + (r * PV_LDA + ldslot) * 2,
                     Bsrc + (size_t)r * kC + k0 + ldslot);
            }
            CP_COMMIT();
            CP_WAIT(1);
        } else {
            CP_WAIT(0);
        }
        __syncthreads();

        #pragma unroll
        for (int ks = 0; ks < 4; ks++) {
            uint32_t af[4][4], bf[4][2];
            #pragma unroll
            for (int mt = 0; mt < 4; mt++)
                ldmx4(af[mt][0], af[mt][1], af[mt][2], af[mt][3],
                      sA[buf] + ((aRow + mt * 16) * PV_LDA + aCol + ks * 16) * 2);
            #pragma unroll
            for (int np = 0; np < 2; np++)
                ldmx4(bf[np * 2][0], bf[np * 2][1], bf[np * 2 + 1][0], bf[np * 2 + 1][1],
                      sB[buf] + ((bRow + np * 16) * PV_LDA + bCol + ks * 16) * 2);
            #pragma unroll
            for (int mt = 0; mt < 4; mt++)
                #pragma unroll
                for (int nt = 0; nt < 4; nt++)
                    mma16816(acc[mt][nt], af[mt], bf[nt]);
        }
        __syncthreads();
    }

    __half* stage = (__half*)smem;        // [128][136]
    constexpr int SLD = 136;
    #pragma unroll
    for (int mt = 0; mt < 4; mt++)
        #pragma unroll
        for (int nt = 0; nt < 4; nt++)
            #pragma unroll
            for (int r = 0; r < 4; r++) {
                int m = wm + mt * 16 + (lane >> 2) + ((r >= 2) ? 8 : 0);
                int n = wn + nt * 8 + (lane & 3) * 2 + (r & 1);
                stage[n * SLD + m] = __float2half_rn(acc[mt][nt][r]);
            }
    __syncthreads();

    const int bz = m0 >> 12;
    const int ml = m0 & 4095;
    #pragma unroll
    for (int q = 0; q < 8; q++) {
        int idx = tid + q * 256;
        int n   = idx >> 4;
        int m8  = (idx & 15) << 3;
        __half* dst = g_vT + ((size_t)bz * kC + n0 + n) * kHW + ml + m8;
        *(uint4*)dst = *(uint4*)(stage + n * SLD + m8);
    }
}

// ========== FUSED: QK^T (3-term split) + online softmax -> fp16 probs ======
// CTA: 128 queries (m0) x one batch. Warp tile 16m x 128n (rows warp-private).
// Smem: Q[128][136] resident; K double buffer; P stage. Two passes over keys:
//   A: online row max/sum (base-2, FMA-pipe exp2).  B: emit probs fp16.
constexpr int AT_LDK  = 136;                        // halves per row (pad 8)
constexpr int AT_TILE = 128 * AT_LDK * 2;           // 34816 B
constexpr int AT_SMEM = 4 * AT_TILE;                // 139264 B

__global__ void __launch_bounds__(256, 1) attn_probs() {
    extern __shared__ char smem[];
    const uint32_t sb = smem_u32(smem);
    const int tid  = threadIdx.x;
    const int lane = tid & 31, wid = tid >> 5;
    const int m0 = blockIdx.x * 128, bz = blockIdx.y;

    const __half* Qsrc = g_qs + ((size_t)bz * kHW + m0) * 128;
    const __half* Ksrc = g_ks + (size_t)bz * kHW * 128;
    __half* Pout = g_sh + (size_t)bz * kHW * kHW + (size_t)m0 * kHW;

    const uint32_t sQ = sb;
    const uint32_t sK[2] = {sb + AT_TILE, sb + 2 * AT_TILE};
    __half* Pstage = (__half*)(smem + 3 * AT_TILE);

    // Q tile resident: 128 rows x 128 halves
    #pragma unroll
    for (int q = 0; q < 8; q++) {
        int idx = tid + q * 256;                 // 0..2047
        int r = idx >> 4, c = (idx & 15) * 8;
        *(uint4*)(smem + (r * AT_LDK + c) * 2) = *(const uint4*)(Qsrc + (size_t)r * 128 + c);
    }

    const int ldrow  = tid >> 4;                 // 0..15
    const int ldslot = (tid & 15) * 8;           // halves

    const int aRow = wid * 16 + (lane & 15);
    const int aCol = (lane >> 4) * 8;
    const int bRowB = ((lane >> 4) << 3) + (lane & 7);
    const int bCol  = ((lane >> 3) & 1) * 8;

    float M2[2] = {-1e30f, -1e30f};
    float Z [2] = {0.f, 0.f};
    float acc[16][4];

// compute S tile for key-tile in buffer `buf` into acc (3-term split QK)
#define AT_COMPUTE(buf)                                                        \
    _Pragma("unroll") for (int nt = 0; nt < 16; nt++)                          \
        _Pragma("unroll") for (int r = 0; r < 4; r++) acc[nt][r] = 0.f;        \
    _Pragma("unroll") for (int term = 0; term < 3; term++) {                   \
        const int ao = (term == 1) ? 64 : 0;                                   \
        const int bo = (term == 2) ? 64 : 0;                                   \
        _Pragma("unroll") for (int ks = 0; ks < 4; ks++) {                     \
            uint32_t af[4], bf[16][2];                                         \
            ldmx4(af[0], af[1], af[2], af[3],                                  \
                  sQ + (aRow * AT_LDK + ao + aCol + ks * 16) * 2);             \
            _Pragma("unroll") for (int np = 0; np < 8; np++)                   \
                ldmx4(bf[np*2][0], bf[np*2][1], bf[np*2+1][0], bf[np*2+1][1],  \
                      sK[buf] + ((bRowB + np * 16) * AT_LDK + bo + bCol + ks * 16) * 2); \
            _Pragma("unroll") for (int nt = 0; nt < 16; nt++)                  \
                mma16816(acc[nt], af, bf[nt]);                                 \
        }                                                                      \
    }

#define AT_PREFETCH(t, buf)                                                    \
    _Pragma("unroll") for (int q = 0; q < 8; q++) {                            \
        int r = q * 16 + ldrow;                                                \
        CP16(sK[buf] + (r * AT_LDK + ldslot) * 2,                              \
             Ksrc + (size_t)((t) * 128 + r) * 128 + ldslot);                   \
    }                                                                          \
    CP_COMMIT();

    // ---------------- Pass A: stats ----------------
    AT_PREFETCH(0, 0)
    for (int t = 0; t < 32; t++) {
        const int buf = t & 1;
        if (t < 31) { AT_PREFETCH(t + 1, buf ^ 1) CP_WAIT(1); }
        else        { CP_WAIT(0); }
        __syncthreads();
        AT_COMPUTE(buf)

        #pragma unroll
        for (int h = 0; h < 2; h++) {
            float lm = -1e30f;
            #pragma unroll
            for (int nt = 0; nt < 16; nt++)
                lm = fmaxf(lm, fmaxf(acc[nt][2*h], acc[nt][2*h+1]));
            lm *= LOG2E;
            lm = fmaxf(lm, __shfl_xor_sync(0xffffffffu, lm, 1));
            lm = fmaxf(lm, __shfl_xor_sync(0xffffffffu, lm, 2));
            float mn = fmaxf(M2[h], lm);
            float s = 0.f;
            #pragma unroll
            for (int nt = 0; nt < 16; nt++) {
                s += exp2f_fast(fmaf(acc[nt][2*h],   LOG2E, -mn));
                s += exp2f_fast(fmaf(acc[nt][2*h+1], LOG2E, -mn));
            }
            s += __shfl_xor_sync(0xffffffffu, s, 1);
            s += __shfl_xor_sync(0xffffffffu, s, 2);
            Z[h] = Z[h] * exp2f_fast(M2[h] - mn) + s;
            M2[h] = mn;
        }
        __syncthreads();
    }

    const float inv0 = 1.f / Z[0];
    const float inv1 = 1.f / Z[1];

    // ---------------- Pass B: emit probs ----------------
    __syncthreads();
    AT_PREFETCH(0, 0)
    for (int t = 0; t < 32; t++) {
        const int buf = t & 1;
        if (t < 31) { AT_PREFETCH(t + 1, buf ^ 1) CP_WAIT(1); }
        else        { CP_WAIT(0); }
        __syncthreads();
        AT_COMPUTE(buf)

        const int prow0 = wid * 16 + (lane >> 2);
        const int pcol  = (lane & 3) * 2;
        #pragma unroll
        for (int nt = 0; nt < 16; nt++) {
            float p0 = exp2f_fast(fmaf(acc[nt][0], LOG2E, -M2[0])) * inv0;
            float p1 = exp2f_fast(fmaf(acc[nt][1], LOG2E, -M2[0])) * inv0;
            float p2 = exp2f_fast(fmaf(acc[nt][2], LOG2E, -M2[1])) * inv1;
            float p3 = exp2f_fast(fmaf(acc[nt][3], LOG2E, -M2[1])) * inv1;
            *(__half2*)(Pstage + prow0       * AT_LDK + nt * 8 + pcol) = __floats2half2_rn(p0, p1);
            *(__half2*)(Pstage + (prow0 + 8) * AT_LDK + nt * 8 + pcol) = __floats2half2_rn(p2, p3);
        }
        __syncthreads();
        #pragma unroll
        for (int q = 0; q < 8; q++) {
            int idx = tid + q * 256;              // 0..2047
            int r = idx >> 4, c = (idx & 15) * 8;
            *(uint4*)(Pout + (size_t)r * kHW + t * 128 + c) = *(uint4*)(Pstage + r * AT_LDK + c);
        }
        __syncthreads();
    }
#undef AT_COMPUTE
#undef AT_PREFETCH
}

// ---------------------------------------------------------------------------
extern "C" void kernel_launch(void* const* d_in, const int* in_sizes, int n_in,
                              void* d_out, int out_size) {
    const float* x     = (const float*)d_in[0];
    const float* W1    = (const float*)d_in[1];
    const float* W2    = (const float*)d_in[2];
    const float* W3    = (const float*)d_in[3];
    const float* gamma = (const float*)d_in[4];
    float* out = (float*)d_out;

    cudaFuncSetAttribute(pv_mma, cudaFuncAttributeMaxDynamicSharedMemorySize, PV_SMEM);
    cudaFuncSetAttribute(vproj_mma, cudaFuncAttributeMaxDynamicSharedMemorySize, PV_SMEM);
    cudaFuncSetAttribute(attn_probs, cudaFuncAttributeMaxDynamicSharedMemorySize, AT_SMEM);

    concat_w<<<256, 256>>>(W1, W2);
    to_half_x<<<8192, 256>>>(x);                          // x fp16 [m][k]
    transpose_w3<<<dim3(16, 16), 256>>>(W3);              // W3^T fp16 [n][k]
    proj_gemm<<<dim3(1, 128), 256>>>(x);                  // q|k fp32 (proven)
    split_qk<<<8192, 256>>>();                            // q,k -> hi/lo fp16
    vproj_mma<<<dim3(4, 128), 256, PV_SMEM>>>();          // vT fp16 (proven)
    attn_probs<<<dim3(32, 4), 256, AT_SMEM>>>();          // fused QK+softmax
    pv_mma<<<dim3(4, 32, 4), 256, PV_SMEM>>>(x, gamma, out);
}

// round 10
// speedup vs baseline: 1.2461x; 1.2461x over previous
#include <cuda_runtime.h>
#include <cuda_fp16.h>
#include <cstdint>

// ---------------------------------------------------------------------------
// PositionAttentionModule: B=4, HW=4096, C=512, Cr=64
//   q|k = x@[W1|W2]      3-term split HMMA (fp32-quality) -> q,k hi/lo fp16
//   v   = x@W3           f16 HMMA NT (proven) -> vT fp16
//   s = q k^T            3-term split HMMA (proven R8) -> fp32 logits
//   softmax rows         FMA-pipe exp2 poly (no MUFU) -> fp16 probs
//   E = s @ v            f16 HMMA NT (proven), fused gamma*E + x
// R10: reverted R9's fused attn (1 CTA/SM occupancy + LDSM-bound => regression).
// Rule R7: device globals referenced ONLY inside kernel bodies.
// ---------------------------------------------------------------------------

constexpr int kHW  = 4096;
constexpr int kC   = 512;
constexpr int kTok = 4 * kHW;   // 16384

__device__ __half g_qs  [kTok * 128];                   // 4 MB q split [hi|lo]
__device__ __half g_ks  [kTok * 128];                   // 4 MB k split [hi|lo]
__device__ float  g_s   [(size_t)4 * kHW * kHW];        // 256 MB fp32 logits
__device__ __half g_sh  [(size_t)4 * kHW * kHW];        // 128 MB fp16 probs
__device__ __half g_vT  [(size_t)4 * kC * kHW];         // 16 MB vT[b][n][i]
__device__ __half g_xh  [(size_t)kTok * kC];            // 16 MB x hi fp16 [m][k]
__device__ __half g_xl  [(size_t)kTok * kC];            // 16 MB x lo fp16 [m][k]
__device__ __half g_w12h[128 * kC];                     // 128 KB W12^T hi [n][k]
__device__ __half g_w12l[128 * kC];                     // 128 KB W12^T lo [n][k]
__device__ __half g_w3T [kC * kC];                      // 512 KB W3^T fp16 [n][k]

// ============================ PTX helpers ==================================
__device__ __forceinline__ uint32_t smem_u32(const void* p) {
    uint32_t a;
    asm("{ .reg .u64 t; cvta.to.shared.u64 t, %1; cvt.u32.u64 %0, t; }"
        : "=r"(a) : "l"(p));
    return a;
}
__device__ __forceinline__ void ldmx4(uint32_t& r0, uint32_t& r1, uint32_t& r2,
                                      uint32_t& r3, uint32_t a) {
    asm volatile("ldmatrix.sync.aligned.m8n8.x4.shared.b16 {%0,%1,%2,%3}, [%4];"
                 : "=r"(r0), "=r"(r1), "=r"(r2), "=r"(r3) : "r"(a));
}
__device__ __forceinline__ void mma16816(float* c, const uint32_t* a,
                                         const uint32_t* b) {
    asm volatile(
        "mma.sync.aligned.m16n8k16.row.col.f32.f16.f16.f32 "
        "{%0,%1,%2,%3}, {%4,%5,%6,%7}, {%8,%9}, {%0,%1,%2,%3};"
        : "+f"(c[0]), "+f"(c[1]), "+f"(c[2]), "+f"(c[3])
        : "r"(a[0]), "r"(a[1]), "r"(a[2]), "r"(a[3]), "r"(b[0]), "r"(b[1]));
}
#define CP16(sm, gp) \
    asm volatile("cp.async.cg.shared.global [%0], [%1], 16;" :: "r"(sm), "l"(gp))
#define CP_COMMIT() asm volatile("cp.async.commit_group;" ::: "memory")
#define CP_WAIT(n)  asm volatile("cp.async.wait_group %0;" :: "n"(n) : "memory")

// exp2 on the FMA pipe (degree-7, rel err ~2e-7)
__device__ __forceinline__ float exp2f_fast(float f) {
    f = fmaxf(f, -126.f);
    float n = floorf(f);
    float r = f - n;
    float p = 1.5252734e-5f;
    p = fmaf(p, r, 1.5403530e-4f);
    p = fmaf(p, r, 1.3333558e-3f);
    p = fmaf(p, r, 9.6181291e-3f);
    p = fmaf(p, r, 5.5504109e-2f);
    p = fmaf(p, r, 2.4022651e-1f);
    p = fmaf(p, r, 6.9314718e-1f);
    p = fmaf(p, r, 1.0f);
    return p * __int_as_float((((int)n) + 127) << 23);
}
constexpr float LOG2E = 1.4426950408889634f;

// ---------------------------------------------------------------------------
// W1,W2 -> W12^T split hi/lo fp16 [n=128][k=512]
__global__ __launch_bounds__(256) void concat_w_split(const float* __restrict__ W1,
                                                      const float* __restrict__ W2) {
    int idx = blockIdx.x * 256 + threadIdx.x;           // < 65536
    int n = idx >> 9, k = idx & 511;
    float v = (n < 64) ? W1[k * 64 + n] : W2[k * 64 + (n - 64)];
    __half hi = __float2half_rn(v);
    __half lo = __float2half_rn(v - __half2float(hi));
    g_w12h[idx] = hi;
    g_w12l[idx] = lo;
}

// x fp32 -> hi/lo fp16
__global__ __launch_bounds__(256) void to_half_x(const float* __restrict__ x) {
    int idx = blockIdx.x * 256 + threadIdx.x;           // < 2097152 (x4)
    float4 v = *(const float4*)(x + (size_t)idx * 4);
    __half h0 = __float2half_rn(v.x), h1 = __float2half_rn(v.y);
    __half h2 = __float2half_rn(v.z), h3 = __float2half_rn(v.w);
    __half2* dh = (__half2*)(g_xh + (size_t)idx * 4);
    dh[0] = __halves2half2(h0, h1);
    dh[1] = __halves2half2(h2, h3);
    __half2* dl = (__half2*)(g_xl + (size_t)idx * 4);
    dl[0] = __floats2half2_rn(v.x - __half2float(h0), v.y - __half2float(h1));
    dl[1] = __floats2half2_rn(v.z - __half2float(h2), v.w - __half2float(h3));
}

__global__ __launch_bounds__(256) void transpose_w3(const float* __restrict__ W3) {
    __shared__ float t[32][33];
    const int tx = threadIdx.x & 31, ty = threadIdx.x >> 5;
    const int n0 = blockIdx.x * 32;
    const int k0 = blockIdx.y * 32;
    #pragma unroll
    for (int j = 0; j < 4; j++) {
        int kk = ty + j * 8;
        t[kk][tx] = W3[(size_t)(k0 + kk) * kC + n0 + tx];
    }
    __syncthreads();
    #pragma unroll
    for (int j = 0; j < 4; j++) {
        int nn = ty + j * 8;
        g_w3T[(size_t)(n0 + nn) * kC + k0 + tx] = __float2half_rn(t[tx][nn]);
    }
}

// Row softmax: fp32 logits in (vec4), FMA-pipe exp2, fp16 probs out
__global__ __launch_bounds__(256) void softmax_rows() {
    const float4* p4 = (const float4*)(g_s + (size_t)blockIdx.x * kHW);
    uint2* ph4 = (uint2*)(g_sh + (size_t)blockIdx.x * kHW);
    const int tid = threadIdx.x;
    __shared__ float red[8], red2[8];

    float4 f[4];
    float m = -1e30f;
    #pragma unroll
    for (int j = 0; j < 4; j++) {
        f[j] = p4[tid + j * 256];
        m = fmaxf(m, fmaxf(fmaxf(f[j].x, f[j].y), fmaxf(f[j].z, f[j].w)));
    }
    #pragma unroll
    for (int o = 16; o > 0; o >>= 1) m = fmaxf(m, __shfl_xor_sync(0xffffffffu, m, o));
    if ((tid & 31) == 0) red[tid >> 5] = m;
    __syncthreads();
    float bm = red[0];
    #pragma unroll
    for (int w = 1; w < 8; w++) bm = fmaxf(bm, red[w]);
    const float bm2 = bm * LOG2E;

    float sum = 0.f;
    #pragma unroll
    for (int j = 0; j < 4; j++) {
        f[j].x = exp2f_fast(fmaf(f[j].x, LOG2E, -bm2));
        f[j].y = exp2f_fast(fmaf(f[j].y, LOG2E, -bm2));
        f[j].z = exp2f_fast(fmaf(f[j].z, LOG2E, -bm2));
        f[j].w = exp2f_fast(fmaf(f[j].w, LOG2E, -bm2));
        sum += (f[j].x + f[j].y) + (f[j].z + f[j].w);
    }
    #pragma unroll
    for (int o = 16; o > 0; o >>= 1) sum += __shfl_xor_sync(0xffffffffu, sum, o);
    if ((tid & 31) == 0) red2[tid >> 5] = sum;
    __syncthreads();
    float bs = 0.f;
    #pragma unroll
    for (int w = 0; w < 8; w++) bs += red2[w];
    float inv = 1.f / bs;
    #pragma unroll
    for (int j = 0; j < 4; j++) {
        __half2 h0 = __floats2half2_rn(f[j].x * inv, f[j].y * inv);
        __half2 h1 = __floats2half2_rn(f[j].z * inv, f[j].w * inv);
        uint2 u;
        u.x = *reinterpret_cast<uint32_t*>(&h0);
        u.y = *reinterpret_cast<uint32_t*>(&h1);
        ph4[tid + j * 256] = u;
    }
}

// ============ HMMA NT skeleton constants ===================================
constexpr int PV_LDA  = 72;                         // halves, padded
constexpr int PV_ABUF = 128 * PV_LDA * 2;           // 18432 B
constexpr int PV_SMEM = 4 * PV_ABUF;                // 73728 B

// ====================== HMMA: PV (E = s @ v), fused epilogue (proven) ======
__global__ void __launch_bounds__(256, 2)
pv_mma(const float* __restrict__ x, const float* __restrict__ gamma,
       float* __restrict__ out) {
    extern __shared__ char smem[];
    const uint32_t sb  = smem_u32(smem);
    const int tid  = threadIdx.x;
    const int lane = tid & 31, wid = tid >> 5;
    const int wm = (wid & 1) * 64, wn = (wid >> 1) * 32;
    const int n0 = blockIdx.x * 128, m0 = blockIdx.y * 128, bz = blockIdx.z;

    const __half* Asrc = g_sh + (size_t)bz * kHW * kHW + (size_t)m0 * kHW;
    const __half* Bsrc = g_vT + (size_t)bz * kC * kHW + (size_t)n0 * kHW;

    const uint32_t sA[2] = {sb, sb + PV_ABUF};
    const uint32_t sB[2] = {sb + 2 * PV_ABUF, sb + 3 * PV_ABUF};

    const int ldrow  = tid >> 3;
    const int ldslot = (tid & 7) * 8;

    float acc[4][4][4];
    #pragma unroll
    for (int i = 0; i < 4; i++)
        #pragma unroll
        for (int j = 0; j < 4; j++)
            #pragma unroll
            for (int r = 0; r < 4; r++) acc[i][j][r] = 0.f;

    const int aRow = wm + (lane & 15);
    const int aCol = (lane >> 4) * 8;
    const int bRow = wn + ((lane >> 4) << 3) + (lane & 7);
    const int bCol = ((lane >> 3) & 1) * 8;

    #pragma unroll
    for (int q = 0; q < 4; q++) {
        int r = q * 32 + ldrow;
        CP16(sA[0] + (r * PV_LDA + ldslot) * 2, Asrc + (size_t)r * kHW + ldslot);
        CP16(sB[0] + (r * PV_LDA + ldslot) * 2, Bsrc + (size_t)r * kHW + ldslot);
    }
    CP_COMMIT();

    for (int i = 0; i < 64; i++) {
        const int buf = i & 1;
        if (i < 63) {
            const int k0 = (i + 1) * 64;
            #pragma unroll
            for (int q = 0; q < 4; q++) {
                int r = q * 32 + ldrow;
                CP16(sA[buf ^ 1] + (r * PV_LDA + ldslot) * 2,
                     Asrc + (size_t)r * kHW + k0 + ldslot);
                CP16(sB[buf ^ 1] + (r * PV_LDA + ldslot) * 2,
                     Bsrc + (size_t)r * kHW + k0 + ldslot);
            }
            CP_COMMIT();
            CP_WAIT(1);
        } else {
            CP_WAIT(0);
        }
        __syncthreads();

        #pragma unroll
        for (int ks = 0; ks < 4; ks++) {
            uint32_t af[4][4], bf[4][2];
            #pragma unroll
            for (int mt = 0; mt < 4; mt++)
                ldmx4(af[mt][0], af[mt][1], af[mt][2], af[mt][3],
                      sA[buf] + ((aRow + mt * 16) * PV_LDA + aCol + ks * 16) * 2);
            #pragma unroll
            for (int np = 0; np < 2; np++)
                ldmx4(bf[np * 2][0], bf[np * 2][1], bf[np * 2 + 1][0], bf[np * 2 + 1][1],
                      sB[buf] + ((bRow + np * 16) * PV_LDA + bCol + ks * 16) * 2);
            #pragma unroll
            for (int mt = 0; mt < 4; mt++)
                #pragma unroll
                for (int nt = 0; nt < 4; nt++)
                    mma16816(acc[mt][nt], af[mt], bf[nt]);
        }
        __syncthreads();
    }

    float* stage = (float*)smem;          // [128][132] as [n][m]
    #pragma unroll
    for (int mt = 0; mt < 4; mt++)
        #pragma unroll
        for (int nt = 0; nt < 4; nt++)
            #pragma unroll
            for (int r = 0; r < 4; r++) {
                int m = wm + mt * 16 + (lane >> 2) + ((r >= 2) ? 8 : 0);
                int n = wn + nt * 8 + (lane & 3) * 2 + (r & 1);
                stage[n * 132 + m] = acc[mt][nt][r];
            }
    __syncthreads();

    const float g = __ldg(gamma);
    const size_t obofs = (size_t)bz * kHW * kC;
    #pragma unroll
    for (int q = 0; q < 16; q++) {
        int idx = tid + q * 256;
        int n   = idx >> 5;
        int m4  = (idx & 31) << 2;
        size_t o = obofs + (size_t)(n0 + n) * kHW + m0 + m4;
        float4 xv = *(const float4*)(x + o);
        const float* sp = stage + n * 132 + m4;
        *(float4*)(out + o) = make_float4(fmaf(g, sp[0], xv.x), fmaf(g, sp[1], xv.y),
                                          fmaf(g, sp[2], xv.z), fmaf(g, sp[3], xv.w));
    }
}

// ============ HMMA: V-proj NT (proven): vT = (x @ W3)^T ====================
__global__ void __launch_bounds__(256, 2) vproj_mma() {
    extern __shared__ char smem[];
    const uint32_t sb  = smem_u32(smem);
    const int tid  = threadIdx.x;
    const int lane = tid & 31, wid = tid >> 5;
    const int wm = (wid & 1) * 64, wn = (wid >> 1) * 32;
    const int n0 = blockIdx.x * 128, m0 = blockIdx.y * 128;

    const __half* Asrc = g_xh + (size_t)m0 * kC;
    const __half* Bsrc = g_w3T + (size_t)n0 * kC;

    const uint32_t sA[2] = {sb, sb + PV_ABUF};
    const uint32_t sB[2] = {sb + 2 * PV_ABUF, sb + 3 * PV_ABUF};

    const int ldrow  = tid >> 3;
    const int ldslot = (tid & 7) * 8;

    float acc[4][4][4];
    #pragma unroll
    for (int i = 0; i < 4; i++)
        #pragma unroll
        for (int j = 0; j < 4; j++)
            #pragma unroll
            for (int r = 0; r < 4; r++) acc[i][j][r] = 0.f;

    const int aRow = wm + (lane & 15);
    const int aCol = (lane >> 4) * 8;
    const int bRow = wn + ((lane >> 4) << 3) + (lane & 7);
    const int bCol = ((lane >> 3) & 1) * 8;

    #pragma unroll
    for (int q = 0; q < 4; q++) {
        int r = q * 32 + ldrow;
        CP16(sA[0] + (r * PV_LDA + ldslot) * 2, Asrc + (size_t)r * kC + ldslot);
        CP16(sB[0] + (r * PV_LDA + ldslot) * 2, Bsrc + (size_t)r * kC + ldslot);
    }
    CP_COMMIT();

    for (int i = 0; i < 8; i++) {
        const int buf = i & 1;
        if (i < 7) {
            const int k0 = (i + 1) * 64;
            #pragma unroll
            for (int q = 0; q < 4; q++) {
                int r = q * 32 + ldrow;
                CP16(sA[buf ^ 1] + (r * PV_LDA + ldslot) * 2,
                     Asrc + (size_t)r * kC + k0 + ldslot);
                CP16(sB[buf ^ 1] + (r * PV_LDA + ldslot) * 2,
                     Bsrc + (size_t)r * kC + k0 + ldslot);
            }
            CP_COMMIT();
            CP_WAIT(1);
        } else {
            CP_WAIT(0);
        }
        __syncthreads();

        #pragma unroll
        for (int ks = 0; ks < 4; ks++) {
            uint32_t af[4][4], bf[4][2];
            #pragma unroll
            for (int mt = 0; mt < 4; mt++)
                ldmx4(af[mt][0], af[mt][1], af[mt][2], af[mt][3],
                      sA[buf] + ((aRow + mt * 16) * PV_LDA + aCol + ks * 16) * 2);
            #pragma unroll
            for (int np = 0; np < 2; np++)
                ldmx4(bf[np * 2][0], bf[np * 2][1], bf[np * 2 + 1][0], bf[np * 2 + 1][1],
                      sB[buf] + ((bRow + np * 16) * PV_LDA + bCol + ks * 16) * 2);
            #pragma unroll
            for (int mt = 0; mt < 4; mt++)
                #pragma unroll
                for (int nt = 0; nt < 4; nt++)
                    mma16816(acc[mt][nt], af[mt], bf[nt]);
        }
        __syncthreads();
    }

    __half* stage = (__half*)smem;        // [128][136]
    constexpr int SLD = 136;
    #pragma unroll
    for (int mt = 0; mt < 4; mt++)
        #pragma unroll
        for (int nt = 0; nt < 4; nt++)
            #pragma unroll
            for (int r = 0; r < 4; r++) {
                int m = wm + mt * 16 + (lane >> 2) + ((r >= 2) ? 8 : 0);
                int n = wn + nt * 8 + (lane & 3) * 2 + (r & 1);
                stage[n * SLD + m] = __float2half_rn(acc[mt][nt][r]);
            }
    __syncthreads();

    const int bz = m0 >> 12;
    const int ml = m0 & 4095;
    #pragma unroll
    for (int q = 0; q < 8; q++) {
        int idx = tid + q * 256;
        int n   = idx >> 4;
        int m8  = (idx & 15) << 3;
        __half* dst = g_vT + ((size_t)bz * kC + n0 + n) * kHW + ml + m8;
        *(uint4*)dst = *(uint4*)(stage + n * SLD + m8);
    }
}

// ===== HMMA: q|k projection via 3-term split (24 chunks), emits hi/lo ======
// qk[m][n] = x_hi.Whi + x_lo.Whi + x_hi.Wlo, m=tokens, n=128 (q|k), K=512.
__global__ void __launch_bounds__(256, 2) qkproj_mma() {
    extern __shared__ char smem[];
    const uint32_t sb  = smem_u32(smem);
    const int tid  = threadIdx.x;
    const int lane = tid & 31, wid = tid >> 5;
    const int wm = (wid & 1) * 64, wn = (wid >> 1) * 32;
    const int m0 = blockIdx.y * 128;

    const uint32_t sA[2] = {sb, sb + PV_ABUF};
    const uint32_t sB[2] = {sb + 2 * PV_ABUF, sb + 3 * PV_ABUF};

    const int ldrow  = tid >> 3;
    const int ldslot = (tid & 7) * 8;

    float acc[4][4][4];
    #pragma unroll
    for (int i = 0; i < 4; i++)
        #pragma unroll
        for (int j = 0; j < 4; j++)
            #pragma unroll
            for (int r = 0; r < 4; r++) acc[i][j][r] = 0.f;

    const int aRow = wm + (lane & 15);
    const int aCol = (lane >> 4) * 8;
    const int bRow = wn + ((lane >> 4) << 3) + (lane & 7);
    const int bCol = ((lane >> 3) & 1) * 8;

    // chunk i (0..23): term = i/8, kc = i%8
    //   A src: term==1 ? g_xl : g_xh ; B src: term==2 ? g_w12l : g_w12h
#define QK_PREFETCH(i, buf) do {                                               \
    const int term = (i) >> 3, kc = (i) & 7;                                   \
    const __half* Ap = ((term == 1) ? g_xl : g_xh) + (size_t)m0 * kC + kc * 64; \
    const __half* Bp = ((term == 2) ? g_w12l : g_w12h) + kc * 64;              \
    _Pragma("unroll") for (int q = 0; q < 4; q++) {                            \
        int r = q * 32 + ldrow;                                                \
        CP16(sA[buf] + (r * PV_LDA + ldslot) * 2, Ap + (size_t)r * kC + ldslot); \
        CP16(sB[buf] + (r * PV_LDA + ldslot) * 2, Bp + (size_t)r * kC + ldslot); \
    }                                                                          \
    CP_COMMIT();                                                               \
} while (0)

    QK_PREFETCH(0, 0);
    for (int i = 0; i < 24; i++) {
        const int buf = i & 1;
        if (i < 23) { QK_PREFETCH(i + 1, buf ^ 1); CP_WAIT(1); }
        else        { CP_WAIT(0); }
        __syncthreads();

        #pragma unroll
        for (int ks = 0; ks < 4; ks++) {
            uint32_t af[4][4], bf[4][2];
            #pragma unroll
            for (int mt = 0; mt < 4; mt++)
                ldmx4(af[mt][0], af[mt][1], af[mt][2], af[mt][3],
                      sA[buf] + ((aRow + mt * 16) * PV_LDA + aCol + ks * 16) * 2);
            #pragma unroll
            for (int np = 0; np < 2; np++)
                ldmx4(bf[np * 2][0], bf[np * 2][1], bf[np * 2 + 1][0], bf[np * 2 + 1][1],
                      sB[buf] + ((bRow + np * 16) * PV_LDA + bCol + ks * 16) * 2);
            #pragma unroll
            for (int mt = 0; mt < 4; mt++)
                #pragma unroll
                for (int nt = 0; nt < 4; nt++)
                    mma16816(acc[mt][nt], af[mt], bf[nt]);
        }
        __syncthreads();
    }
#undef QK_PREFETCH

    // stage [m][n] fp32 -> split hi/lo into g_qs (n<64) / g_ks (n>=64)
    float* stage = (float*)smem;          // [128][132]
    #pragma unroll
    for (int mt = 0; mt < 4; mt++)
        #pragma unroll
        for (int nt = 0; nt < 4; nt++)
            #pragma unroll
            for (int r = 0; r < 4; r++) {
                int m = wm + mt * 16 + (lane >> 2) + ((r >= 2) ? 8 : 0);
                int n = wn + nt * 8 + (lane & 3) * 2 + (r & 1);
                stage[m * 132 + n] = acc[mt][nt][r];
            }
    __syncthreads();

    #pragma unroll
    for (int q = 0; q < 16; q++) {
        int idx = tid + q * 256;          // 0..4095
        int t   = idx >> 5;               // token within tile
        int c4  = (idx & 31) << 2;        // col group of 4 (entirely in q or k)
        const float* sp = stage + t * 132 + c4;
        __half hi[4], lo[4];
        #pragma unroll
        for (int j = 0; j < 4; j++) {
            hi[j] = __float2half_rn(sp[j]);
            lo[j] = __float2half_rn(sp[j] - __half2float(hi[j]));
        }
        __half* base = (c4 < 64) ? (g_qs + (size_t)(m0 + t) * 128 + c4)
                                 : (g_ks + (size_t)(m0 + t) * 128 + (c4 - 64));
        *(uint2*)base        = *(uint2*)hi;
        *(uint2*)(base + 64) = *(uint2*)lo;
    }
}

// ========== HMMA: logits via exact 3-term fp16 split (proven R8) ===========
__global__ void __launch_bounds__(256, 2) logits_split() {
    extern __shared__ char smem[];
    const uint32_t sb  = smem_u32(smem);
    const int tid  = threadIdx.x;
    const int lane = tid & 31, wid = tid >> 5;
    const int wm = (wid & 1) * 64, wn = (wid >> 1) * 32;
    const int n0 = blockIdx.x * 128, m0 = blockIdx.y * 128, bz = blockIdx.z;

    const __half* Asrc = g_qs + ((size_t)bz * kHW + m0) * 128;
    const __half* Bsrc = g_ks + ((size_t)bz * kHW + n0) * 128;

    const uint32_t sA[2] = {sb, sb + PV_ABUF};
    const uint32_t sB[2] = {sb + 2 * PV_ABUF, sb + 3 * PV_ABUF};

    const int ldrow  = tid >> 3;
    const int ldslot = (tid & 7) * 8;

    float acc[4][4][4];
    #pragma unroll
    for (int i = 0; i < 4; i++)
        #pragma unroll
        for (int j = 0; j < 4; j++)
            #pragma unroll
            for (int r = 0; r < 4; r++) acc[i][j][r] = 0.f;

    const int aRow = wm + (lane & 15);
    const int aCol = (lane >> 4) * 8;
    const int bRow = wn + ((lane >> 4) << 3) + (lane & 7);
    const int bCol = ((lane >> 3) & 1) * 8;

    const int AOFF[3] = {0, 64, 0};
    const int BOFF[3] = {0, 0, 64};

    #pragma unroll
    for (int q = 0; q < 4; q++) {
        int r = q * 32 + ldrow;
        CP16(sA[0] + (r * PV_LDA + ldslot) * 2, Asrc + (size_t)r * 128 + AOFF[0] + ldslot);
        CP16(sB[0] + (r * PV_LDA + ldslot) * 2, Bsrc + (size_t)r * 128 + BOFF[0] + ldslot);
    }
    CP_COMMIT();

    for (int i = 0; i < 3; i++) {
        const int buf = i & 1;
        if (i < 2) {
            #pragma unroll
            for (int q = 0; q < 4; q++) {
                int r = q * 32 + ldrow;
                CP16(sA[buf ^ 1] + (r * PV_LDA + ldslot) * 2,
                     Asrc + (size_t)r * 128 + AOFF[i + 1] + ldslot);
                CP16(sB[buf ^ 1] + (r * PV_LDA + ldslot) * 2,
                     Bsrc + (size_t)r * 128 + BOFF[i + 1] + ldslot);
            }
            CP_COMMIT();
            CP_WAIT(1);
        } else {
            CP_WAIT(0);
        }
        __syncthreads();

        #pragma unroll
        for (int ks = 0; ks < 4; ks++) {
            uint32_t af[4][4], bf[4][2];
            #pragma unroll
            for (int mt = 0; mt < 4; mt++)
                ldmx4(af[mt][0], af[mt][1], af[mt][2], af[mt][3],
                      sA[buf] + ((aRow + mt * 16) * PV_LDA + aCol + ks * 16) * 2);
            #pragma unroll
            for (int np = 0; np < 2; np++)
                ldmx4(bf[np * 2][0], bf[np * 2][1], bf[np * 2 + 1][0], bf[np * 2 + 1][1],
                      sB[buf] + ((bRow + np * 16) * PV_LDA + bCol + ks * 16) * 2);
            #pragma unroll
            for (int mt = 0; mt < 4; mt++)
                #pragma unroll
                for (int nt = 0; nt < 4; nt++)
                    mma16816(acc[mt][nt], af[mt], bf[nt]);
        }
        __syncthreads();
    }

    float* stage = (float*)smem;          // [128][132] as [m][n]
    #pragma unroll
    for (int mt = 0; mt < 4; mt++)
        #pragma unroll
        for (int nt = 0; nt < 4; nt++)
            #pragma unroll
            for (int r = 0; r < 4; r++) {
                int m = wm + mt * 16 + (lane >> 2) + ((r >= 2) ? 8 : 0);
                int n = wn + nt * 8 + (lane & 3) * 2 + (r & 1);
                stage[m * 132 + n] = acc[mt][nt][r];
            }
    __syncthreads();

    float* Cp = g_s + (size_t)bz * kHW * kHW;
    #pragma unroll
    for (int q = 0; q < 16; q++) {
        int idx = tid + q * 256;
        int m   = idx >> 5;
        int n4  = (idx & 31) << 2;
        *(float4*)(Cp + (size_t)(m0 + m) * kHW + n0 + n4) = *(float4*)(stage + m * 132 + n4);
    }
}

// ---------------------------------------------------------------------------
extern "C" void kernel_launch(void* const* d_in, const int* in_sizes, int n_in,
                              void* d_out, int out_size) {
    const float* x     = (const float*)d_in[0];
    const float* W1    = (const float*)d_in[1];
    const float* W2    = (const float*)d_in[2];
    const float* W3    = (const float*)d_in[3];
    const float* gamma = (const float*)d_in[4];
    float* out = (float*)d_out;

    cudaFuncSetAttribute(pv_mma, cudaFuncAttributeMaxDynamicSharedMemorySize, PV_SMEM);
    cudaFuncSetAttribute(vproj_mma, cudaFuncAttributeMaxDynamicSharedMemorySize, PV_SMEM);
    cudaFuncSetAttribute(qkproj_mma, cudaFuncAttributeMaxDynamicSharedMemorySize, PV_SMEM);
    cudaFuncSetAttribute(logits_split, cudaFuncAttributeMaxDynamicSharedMemorySize, PV_SMEM);

    concat_w_split<<<256, 256>>>(W1, W2);                 // W12^T hi/lo
    to_half_x<<<8192, 256>>>(x);                          // x hi/lo fp16
    transpose_w3<<<dim3(16, 16), 256>>>(W3);              // W3^T fp16
    qkproj_mma<<<dim3(1, 128), 256, PV_SMEM>>>();         // q,k hi/lo (split HMMA)
    vproj_mma<<<dim3(4, 128), 256, PV_SMEM>>>();          // vT fp16 (proven)
    logits_split<<<dim3(32, 32, 4), 256, PV_SMEM>>>();    // fp32 logits (proven)
    softmax_rows<<<16384, 256>>>();                       // fp16 probs (FMA exp2)
    pv_mma<<<dim3(4, 32, 4), 256, PV_SMEM>>>(x, gamma, out);
}